// round 6
// baseline (speedup 1.0000x reference)
#include <cuda_runtime.h>
#include <math.h>

// GPT-2 small forward: 3-stage cp.async tf32 tensor GEMMs (flattened fragment pipeline)
// + tiled fp32 flash attention.
// B=2, T=1024, C=768, H=12, HD=64, L=12, V=50257.

#define Bsz 2
#define Tlen 1024
#define BT (Bsz * Tlen)      // 2048
#define C 768
#define H 12
#define HD 64
#define NL 12
#define V 50257
#define VP 50304             // V padded to multiple of 128 (16B-aligned rows)
#define C3 (3 * C)           // 2304
#define C4 (4 * C)           // 3072
#define EPS 1e-5f

// ---------------- scratch ----------------
__device__ float g_x[BT * C];
__device__ float g_ln[BT * C];
__device__ float g_qkv[BT * C3];
__device__ float g_atty[BT * C];
__device__ float g_h[BT * C4];
__device__ float g_wpad[(long long)C * VP];   // padded lm_head weights

// ---------------- embedding ----------------
__global__ void embed_kernel(const int* __restrict__ idx,
                             const float* __restrict__ wte,
                             const float* __restrict__ wpe,
                             float* __restrict__ out) {
    int row = blockIdx.x;
    int tpos = row % Tlen;
    int tok = idx[row];
    const float* we = wte + (long long)tok * C;
    const float* pe = wpe + (long long)tpos * C;
    float* o = out + (long long)row * C;
    for (int c = threadIdx.x; c < C; c += blockDim.x)
        o[c] = we[c] + pe[c];
}

// ---------------- lm_head weight padding ----------------
__global__ void padw_kernel(const float* __restrict__ w, float* __restrict__ wp) {
    int k = blockIdx.y;
    int n = blockIdx.x * blockDim.x + threadIdx.x;
    if (n < VP)
        wp[(long long)k * VP + n] = (n < V) ? w[(long long)k * V + n] : 0.f;
}

// ---------------- layernorm ----------------
__global__ void ln_kernel(const float* __restrict__ x,
                          const float* __restrict__ w,
                          const float* __restrict__ b,
                          float* __restrict__ out) {
    __shared__ float red[256];
    __shared__ float red2[256];
    int row = blockIdx.x;
    const float* xr = x + (long long)row * C;
    float s = 0.f, sq = 0.f;
    for (int c = threadIdx.x; c < C; c += blockDim.x) {
        float v = xr[c];
        s += v; sq += v * v;
    }
    red[threadIdx.x] = s; red2[threadIdx.x] = sq;
    __syncthreads();
    for (int off = 128; off > 0; off >>= 1) {
        if (threadIdx.x < off) {
            red[threadIdx.x] += red[threadIdx.x + off];
            red2[threadIdx.x] += red2[threadIdx.x + off];
        }
        __syncthreads();
    }
    float mean = red[0] / C;
    float var = red2[0] / C - mean * mean;
    float rstd = rsqrtf(var + EPS);
    float* o = out + (long long)row * C;
    for (int c = threadIdx.x; c < C; c += blockDim.x)
        o[c] = (xr[c] - mean) * rstd * w[c] + b[c];
}

// ---------------- helpers ----------------
__device__ __forceinline__ float gelu_f(float x) {
    float x3 = x * x * x;
    return 0.5f * x * (1.f + tanhf(0.7978845608028654f * (x + 0.044715f * x3)));
}

__device__ __forceinline__ unsigned tf32_of(float f) {
    unsigned u;
    asm("cvt.rna.tf32.f32 %0, %1;" : "=r"(u) : "f"(f));
    return u;
}

__device__ __forceinline__ unsigned sptr(const void* p) {
    return (unsigned)__cvta_generic_to_shared(p);
}

// ---------------- 3-stage cp.async tf32 GEMM (flattened fragments) ----------------
// out[M,N] = A[M,K] @ W[K,N] (W row stride ldw); epi: 0=+bias, 1=gelu, 2=+residual, 3=none
// 128 threads (4 warps 2x2), tile BM x 128, warp tile (BM/2) x 64, K-tile 16, 3 stages.
#define ASTR 20      // 16 + 4 pad
#define BSTR 136     // 128 + 8 pad

template<int BM>
__global__ void __launch_bounds__(128)
tgemm_kernel(const float* __restrict__ A, const float* __restrict__ W,
             const float* __restrict__ bias, float* __restrict__ out,
             int M, int N, int K, int ldw, int epi) {
    constexpr int MI = BM / 32;
    extern __shared__ float sm[];
    float* As = sm;                       // 3 stages of BM*ASTR
    float* Bs = sm + 3 * BM * ASTR;       // 3 stages of 16*BSTR

    int tid = threadIdx.x;
    int w = tid >> 5, lane = tid & 31;
    int g = lane >> 2, tig = lane & 3;
    int wm = (w & 1) * (BM / 2);
    int wn = (w >> 1) * 64;
    int m0 = blockIdx.y * BM;
    int n0 = blockIdx.x * 128;

    float acc[MI][8][4];
#pragma unroll
    for (int mi = 0; mi < MI; mi++)
#pragma unroll
        for (int nj = 0; nj < 8; nj++)
#pragma unroll
            for (int r = 0; r < 4; r++) acc[mi][nj][r] = 0.f;

    auto loadTiles = [&](int kt, int s) {
        int k0 = kt * 16;
        float* as = As + s * (BM * ASTR);
        float* bs = Bs + s * (16 * BSTR);
#pragma unroll
        for (int i = 0; i < BM / 32; i++) {
            int id = tid + i * 128;
            int row = id >> 2, kc = (id & 3) * 4;
            unsigned dst = sptr(&as[row * ASTR + kc]);
            const float* src = A + (long long)(m0 + row) * K + k0 + kc;
            asm volatile("cp.async.cg.shared.global [%0], [%1], 16;" :: "r"(dst), "l"(src));
        }
#pragma unroll
        for (int i = 0; i < 4; i++) {
            int id = tid + i * 128;
            int row = id >> 5, nc = (id & 31) * 4;
            unsigned dst = sptr(&bs[row * BSTR + nc]);
            const float* src = W + (long long)(k0 + row) * ldw + n0 + nc;
            asm volatile("cp.async.cg.shared.global [%0], [%1], 16;" :: "r"(dst), "l"(src));
        }
    };

    int nk = K / 16;
    loadTiles(0, 0);
    asm volatile("cp.async.commit_group;");
    loadTiles(1, 1);
    asm volatile("cp.async.commit_group;");

    for (int kt = 0; kt < nk; kt++) {
        asm volatile("cp.async.wait_group 1;");
        __syncthreads();

        // issue next-tile DMA immediately: overlaps the whole compute phase.
        // stage (kt+2)%3 == (kt-1)%3; its readers finished before the barrier above.
        if (kt + 2 < nk) loadTiles(kt + 2, (kt + 2) % 3);
        asm volatile("cp.async.commit_group;");

        int cur = kt % 3;
        const float* as = As + cur * (BM * ASTR);
        const float* bs = Bs + cur * (16 * BSTR);

        // ---- load + convert ALL fragments (both kk phases) up front ----
        unsigned af[2][MI][4], bf[2][8][2];
#pragma unroll
        for (int kk = 0; kk < 2; kk++) {
#pragma unroll
            for (int mi = 0; mi < MI; mi++) {
                int r = wm + mi * 16 + g;
                af[kk][mi][0] = tf32_of(as[r * ASTR + kk * 8 + tig]);
                af[kk][mi][1] = tf32_of(as[(r + 8) * ASTR + kk * 8 + tig]);
                af[kk][mi][2] = tf32_of(as[r * ASTR + kk * 8 + tig + 4]);
                af[kk][mi][3] = tf32_of(as[(r + 8) * ASTR + kk * 8 + tig + 4]);
            }
#pragma unroll
            for (int nj = 0; nj < 8; nj++) {
                int col = wn + nj * 8 + g;
                bf[kk][nj][0] = tf32_of(bs[(kk * 8 + tig) * BSTR + col]);
                bf[kk][nj][1] = tf32_of(bs[(kk * 8 + tig + 4) * BSTR + col]);
            }
        }

        // ---- dense MMA burst: 2 * MI * 8 independent MMAs ----
#pragma unroll
        for (int kk = 0; kk < 2; kk++)
#pragma unroll
            for (int mi = 0; mi < MI; mi++)
#pragma unroll
                for (int nj = 0; nj < 8; nj++)
                    asm volatile(
                        "mma.sync.aligned.m16n8k8.row.col.f32.tf32.tf32.f32 "
                        "{%0,%1,%2,%3},{%4,%5,%6,%7},{%8,%9},{%0,%1,%2,%3};\n"
                        : "+f"(acc[mi][nj][0]), "+f"(acc[mi][nj][1]),
                          "+f"(acc[mi][nj][2]), "+f"(acc[mi][nj][3])
                        : "r"(af[kk][mi][0]), "r"(af[kk][mi][1]),
                          "r"(af[kk][mi][2]), "r"(af[kk][mi][3]),
                          "r"(bf[kk][nj][0]), "r"(bf[kk][nj][1]));
    }

    // ---- epilogue ----
#pragma unroll
    for (int mi = 0; mi < MI; mi++) {
        int r0 = m0 + wm + mi * 16 + g;
#pragma unroll
        for (int nj = 0; nj < 8; nj++) {
            int col = n0 + wn + nj * 8 + 2 * tig;
#pragma unroll
            for (int half = 0; half < 2; half++) {
                int rr = r0 + half * 8;
#pragma unroll
                for (int jj = 0; jj < 2; jj++) {
                    int cc = col + jj;
                    if (cc < N) {
                        float v = acc[mi][nj][half * 2 + jj];
                        if (epi != 3) v += bias[cc];
                        if (epi == 1) v = gelu_f(v);
                        long long o = (long long)rr * N + cc;
                        if (epi == 2) v += out[o];
                        out[o] = v;
                    }
                }
            }
        }
    }
}

// ---------------- tiled fp32 flash attention ----------------
// Block: 64 queries x 1 head, kv tiles of 64. 256 threads = 16(ty: 4 q) x 16(tx).
__global__ void __launch_bounds__(256)
fattn_kernel(const float* __restrict__ qkv, float* __restrict__ out) {
    extern __shared__ float sm[];
    float (*sQt)[68] = (float(*)[68])(sm);              // [d][q]
    float (*sKt)[68] = (float(*)[68])(sm + 64 * 68);    // [d][kv]
    float (*sV)[68]  = (float(*)[68])(sm + 2 * 64 * 68);// [kv][d]
    float (*sP)[68]  = (float(*)[68])(sm + 3 * 64 * 68);// [q][kv]

    int tid = threadIdx.x;
    int tx = tid & 15, ty = tid >> 4;
    int qt = (int)gridDim.x - 1 - (int)blockIdx.x;  // heavy tiles first
    int h = blockIdx.y, b = blockIdx.z;
    int q0 = qt * 64;

    {
        int r = tid >> 4;
        int c4 = (tid & 15) * 4;
#pragma unroll
        for (int rr = 0; rr < 64; rr += 16) {
            const float* qrow = qkv + (long long)(b * Tlen + q0 + r + rr) * C3 + h * HD;
            float4 v = *(const float4*)(qrow + c4);
            sQt[c4 + 0][r + rr] = v.x;
            sQt[c4 + 1][r + rr] = v.y;
            sQt[c4 + 2][r + rr] = v.z;
            sQt[c4 + 3][r + rr] = v.w;
        }
    }

    float O[4][4] = {};
    float m[4], l[4];
#pragma unroll
    for (int i = 0; i < 4; i++) { m[i] = -INFINITY; l[i] = 0.f; }

    const float scale = 0.125f;
    int ntiles = qt + 1;

    for (int kt = 0; kt < ntiles; kt++) {
        int kv0 = kt * 64;
        __syncthreads();
        {
            int r = tid >> 4;
            int c4 = (tid & 15) * 4;
#pragma unroll
            for (int rr0 = 0; rr0 < 64; rr0 += 16) {
                int rr = r + rr0;
                const float* krow = qkv + (long long)(b * Tlen + kv0 + rr) * C3 + C + h * HD;
                float4 kv4 = *(const float4*)(krow + c4);
                sKt[c4 + 0][rr] = kv4.x;
                sKt[c4 + 1][rr] = kv4.y;
                sKt[c4 + 2][rr] = kv4.z;
                sKt[c4 + 3][rr] = kv4.w;
                const float* vrow = qkv + (long long)(b * Tlen + kv0 + rr) * C3 + 2 * C + h * HD;
                *(float4*)&sV[rr][c4] = *(const float4*)(vrow + c4);
            }
        }
        __syncthreads();

        float s[4][4] = {};
#pragma unroll 16
        for (int kk = 0; kk < 64; kk++) {
            float4 a = *(const float4*)&sQt[kk][ty * 4];
            float4 bv = *(const float4*)&sKt[kk][tx * 4];
            s[0][0] += a.x * bv.x; s[0][1] += a.x * bv.y; s[0][2] += a.x * bv.z; s[0][3] += a.x * bv.w;
            s[1][0] += a.y * bv.x; s[1][1] += a.y * bv.y; s[1][2] += a.y * bv.z; s[1][3] += a.y * bv.w;
            s[2][0] += a.z * bv.x; s[2][1] += a.z * bv.y; s[2][2] += a.z * bv.z; s[2][3] += a.z * bv.w;
            s[3][0] += a.w * bv.x; s[3][1] += a.w * bv.y; s[3][2] += a.w * bv.z; s[3][3] += a.w * bv.w;
        }
#pragma unroll
        for (int i = 0; i < 4; i++)
#pragma unroll
            for (int j = 0; j < 4; j++) s[i][j] *= scale;

        if (kt == qt) {
#pragma unroll
            for (int i = 0; i < 4; i++) {
                int qg = q0 + ty * 4 + i;
#pragma unroll
                for (int j = 0; j < 4; j++)
                    if (kv0 + tx * 4 + j > qg) s[i][j] = -INFINITY;
            }
        }

#pragma unroll
        for (int i = 0; i < 4; i++) {
            float rm = fmaxf(fmaxf(s[i][0], s[i][1]), fmaxf(s[i][2], s[i][3]));
#pragma unroll
            for (int off = 1; off < 16; off <<= 1)
                rm = fmaxf(rm, __shfl_xor_sync(0xFFFFFFFFu, rm, off));
            float mn = fmaxf(m[i], rm);
            float cs = __expf(m[i] - mn);
            float p0 = __expf(s[i][0] - mn);
            float p1 = __expf(s[i][1] - mn);
            float p2 = __expf(s[i][2] - mn);
            float p3 = __expf(s[i][3] - mn);
            float rs = (p0 + p1) + (p2 + p3);
#pragma unroll
            for (int off = 1; off < 16; off <<= 1)
                rs += __shfl_xor_sync(0xFFFFFFFFu, rs, off);
            l[i] = l[i] * cs + rs;
            m[i] = mn;
            O[i][0] *= cs; O[i][1] *= cs; O[i][2] *= cs; O[i][3] *= cs;
            sP[ty * 4 + i][tx * 4 + 0] = p0;
            sP[ty * 4 + i][tx * 4 + 1] = p1;
            sP[ty * 4 + i][tx * 4 + 2] = p2;
            sP[ty * 4 + i][tx * 4 + 3] = p3;
        }
        __syncthreads();

#pragma unroll 8
        for (int kv = 0; kv < 64; kv++) {
            float4 v = *(const float4*)&sV[kv][tx * 4];
            float p0 = sP[ty * 4 + 0][kv];
            float p1 = sP[ty * 4 + 1][kv];
            float p2 = sP[ty * 4 + 2][kv];
            float p3 = sP[ty * 4 + 3][kv];
            O[0][0] += p0 * v.x; O[0][1] += p0 * v.y; O[0][2] += p0 * v.z; O[0][3] += p0 * v.w;
            O[1][0] += p1 * v.x; O[1][1] += p1 * v.y; O[1][2] += p1 * v.z; O[1][3] += p1 * v.w;
            O[2][0] += p2 * v.x; O[2][1] += p2 * v.y; O[2][2] += p2 * v.z; O[2][3] += p2 * v.w;
            O[3][0] += p3 * v.x; O[3][1] += p3 * v.y; O[3][2] += p3 * v.z; O[3][3] += p3 * v.w;
        }
    }

#pragma unroll
    for (int i = 0; i < 4; i++) {
        float inv = 1.f / l[i];
        float4 o4;
        o4.x = O[i][0] * inv; o4.y = O[i][1] * inv;
        o4.z = O[i][2] * inv; o4.w = O[i][3] * inv;
        float* o = out + (long long)(b * Tlen + q0 + ty * 4 + i) * C + h * HD + tx * 4;
        *(float4*)o = o4;
    }
}

// ---------------- driver ----------------
#define GEMM_SMEM(BM) (3 * ((BM) * ASTR + 16 * BSTR) * (int)sizeof(float))
#define ATTN_SMEM (4 * 64 * 68 * (int)sizeof(float))

extern "C" void kernel_launch(void* const* d_in, const int* in_sizes, int n_in,
                              void* d_out, int out_size) {
    const int*   idx      = (const int*)  d_in[0];
    const float* wte      = (const float*)d_in[1];
    const float* wpe      = (const float*)d_in[2];
    const float* ln1_w    = (const float*)d_in[3];
    const float* ln1_b    = (const float*)d_in[4];
    const float* attn_w   = (const float*)d_in[5];
    const float* attn_b   = (const float*)d_in[6];
    const float* proj_w   = (const float*)d_in[7];
    const float* proj_b   = (const float*)d_in[8];
    const float* ln2_w    = (const float*)d_in[9];
    const float* ln2_b    = (const float*)d_in[10];
    const float* fc_w     = (const float*)d_in[11];
    const float* fc_b     = (const float*)d_in[12];
    const float* fcproj_w = (const float*)d_in[13];
    const float* fcproj_b = (const float*)d_in[14];
    const float* lnf_w    = (const float*)d_in[15];
    const float* lnf_b    = (const float*)d_in[16];
    const float* lm_head  = (const float*)d_in[17];
    float* out = (float*)d_out;

    float *x, *ln, *qkv, *atty, *hbuf, *wpad;
    cudaGetSymbolAddress((void**)&x,    g_x);
    cudaGetSymbolAddress((void**)&ln,   g_ln);
    cudaGetSymbolAddress((void**)&qkv,  g_qkv);
    cudaGetSymbolAddress((void**)&atty, g_atty);
    cudaGetSymbolAddress((void**)&hbuf, g_h);
    cudaGetSymbolAddress((void**)&wpad, g_wpad);

    cudaFuncSetAttribute(tgemm_kernel<128>,
                         cudaFuncAttributeMaxDynamicSharedMemorySize, GEMM_SMEM(128));
    cudaFuncSetAttribute(tgemm_kernel<64>,
                         cudaFuncAttributeMaxDynamicSharedMemorySize, GEMM_SMEM(64));
    cudaFuncSetAttribute(fattn_kernel,
                         cudaFuncAttributeMaxDynamicSharedMemorySize, ATTN_SMEM);

    embed_kernel<<<BT, 256>>>(idx, wte, wpe, x);
    padw_kernel<<<dim3((VP + 255) / 256, C), 256>>>(lm_head, wpad);

    for (int l = 0; l < NL; l++) {
        ln_kernel<<<BT, 256>>>(x, ln1_w + l * C, ln1_b + l * C, ln);
        tgemm_kernel<128><<<dim3(C3 / 128, BT / 128), 128, GEMM_SMEM(128)>>>(
            ln, attn_w + (long long)l * C * C3, attn_b + l * C3, qkv, BT, C3, C, C3, 0);
        fattn_kernel<<<dim3(Tlen / 64, H, Bsz), 256, ATTN_SMEM>>>(qkv, atty);
        tgemm_kernel<64><<<dim3(C / 128, BT / 64), 128, GEMM_SMEM(64)>>>(
            atty, proj_w + (long long)l * C * C, proj_b + l * C, x, BT, C, C, C, 2);
        ln_kernel<<<BT, 256>>>(x, ln2_w + l * C, ln2_b + l * C, ln);
        tgemm_kernel<128><<<dim3(C4 / 128, BT / 128), 128, GEMM_SMEM(128)>>>(
            ln, fc_w + (long long)l * C * C4, fc_b + l * C4, hbuf, BT, C4, C, C4, 1);
        tgemm_kernel<64><<<dim3(C / 128, BT / 64), 128, GEMM_SMEM(64)>>>(
            hbuf, fcproj_w + (long long)l * C4 * C, fcproj_b + l * C, x, BT, C, C4, C, 2);
    }

    ln_kernel<<<BT, 256>>>(x, lnf_w, lnf_b, ln);
    tgemm_kernel<128><<<dim3(VP / 128, BT / 128), 128, GEMM_SMEM(128)>>>(
        ln, wpad, (const float*)nullptr, out, BT, V, C, VP, 3);
}

// round 7
// speedup vs baseline: 1.0019x; 1.0019x over previous
#include <cuda_runtime.h>
#include <math.h>

// GPT-2 small forward: 3-stage cp.async tf32 tensor GEMMs (flattened fragment pipeline)
// + tiled fp32 flash attention.
// B=2, T=1024, C=768, H=12, HD=64, L=12, V=50257.

#define Bsz 2
#define Tlen 1024
#define BT (Bsz * Tlen)      // 2048
#define C 768
#define H 12
#define HD 64
#define NL 12
#define V 50257
#define VP 50304             // V padded to multiple of 128 (16B-aligned rows)
#define C3 (3 * C)           // 2304
#define C4 (4 * C)           // 3072
#define EPS 1e-5f

// ---------------- scratch ----------------
__device__ float g_x[BT * C];
__device__ float g_ln[BT * C];
__device__ float g_qkv[BT * C3];
__device__ float g_atty[BT * C];
__device__ float g_h[BT * C4];
__device__ float g_wpad[(long long)C * VP];   // padded lm_head weights

// ---------------- embedding ----------------
__global__ void embed_kernel(const int* __restrict__ idx,
                             const float* __restrict__ wte,
                             const float* __restrict__ wpe,
                             float* __restrict__ out) {
    int row = blockIdx.x;
    int tpos = row % Tlen;
    int tok = idx[row];
    const float* we = wte + (long long)tok * C;
    const float* pe = wpe + (long long)tpos * C;
    float* o = out + (long long)row * C;
    for (int c = threadIdx.x; c < C; c += blockDim.x)
        o[c] = we[c] + pe[c];
}

// ---------------- lm_head weight padding ----------------
__global__ void padw_kernel(const float* __restrict__ w, float* __restrict__ wp) {
    int k = blockIdx.y;
    int n = blockIdx.x * blockDim.x + threadIdx.x;
    if (n < VP)
        wp[(long long)k * VP + n] = (n < V) ? w[(long long)k * V + n] : 0.f;
}

// ---------------- layernorm ----------------
__global__ void ln_kernel(const float* __restrict__ x,
                          const float* __restrict__ w,
                          const float* __restrict__ b,
                          float* __restrict__ out) {
    __shared__ float red[256];
    __shared__ float red2[256];
    int row = blockIdx.x;
    const float* xr = x + (long long)row * C;
    float s = 0.f, sq = 0.f;
    for (int c = threadIdx.x; c < C; c += blockDim.x) {
        float v = xr[c];
        s += v; sq += v * v;
    }
    red[threadIdx.x] = s; red2[threadIdx.x] = sq;
    __syncthreads();
    for (int off = 128; off > 0; off >>= 1) {
        if (threadIdx.x < off) {
            red[threadIdx.x] += red[threadIdx.x + off];
            red2[threadIdx.x] += red2[threadIdx.x + off];
        }
        __syncthreads();
    }
    float mean = red[0] / C;
    float var = red2[0] / C - mean * mean;
    float rstd = rsqrtf(var + EPS);
    float* o = out + (long long)row * C;
    for (int c = threadIdx.x; c < C; c += blockDim.x)
        o[c] = (xr[c] - mean) * rstd * w[c] + b[c];
}

// ---------------- helpers ----------------
__device__ __forceinline__ float gelu_f(float x) {
    float x3 = x * x * x;
    return 0.5f * x * (1.f + tanhf(0.7978845608028654f * (x + 0.044715f * x3)));
}

__device__ __forceinline__ unsigned tf32_of(float f) {
    unsigned u;
    asm("cvt.rna.tf32.f32 %0, %1;" : "=r"(u) : "f"(f));
    return u;
}

__device__ __forceinline__ unsigned sptr(const void* p) {
    return (unsigned)__cvta_generic_to_shared(p);
}

// ---------------- 3-stage cp.async tf32 GEMM (flattened fragments) ----------------
// out[M,N] = A[M,K] @ W[K,N] (W row stride ldw); epi: 0=+bias, 1=gelu, 2=+residual, 3=none
// 128 threads (4 warps 2x2), tile BM x 128, warp tile (BM/2) x 64, K-tile 16, 3 stages.
#define ASTR 20      // 16 + 4 pad
#define BSTR 136     // 128 + 8 pad

template<int BM>
__global__ void __launch_bounds__(128)
tgemm_kernel(const float* __restrict__ A, const float* __restrict__ W,
             const float* __restrict__ bias, float* __restrict__ out,
             int M, int N, int K, int ldw, int epi) {
    constexpr int MI = BM / 32;
    extern __shared__ float sm[];
    float* As = sm;                       // 3 stages of BM*ASTR
    float* Bs = sm + 3 * BM * ASTR;       // 3 stages of 16*BSTR

    int tid = threadIdx.x;
    int w = tid >> 5, lane = tid & 31;
    int g = lane >> 2, tig = lane & 3;
    int wm = (w & 1) * (BM / 2);
    int wn = (w >> 1) * 64;
    int m0 = blockIdx.y * BM;
    int n0 = blockIdx.x * 128;

    float acc[MI][8][4];
#pragma unroll
    for (int mi = 0; mi < MI; mi++)
#pragma unroll
        for (int nj = 0; nj < 8; nj++)
#pragma unroll
            for (int r = 0; r < 4; r++) acc[mi][nj][r] = 0.f;

    auto loadTiles = [&](int kt, int s) {
        int k0 = kt * 16;
        float* as = As + s * (BM * ASTR);
        float* bs = Bs + s * (16 * BSTR);
#pragma unroll
        for (int i = 0; i < BM / 32; i++) {
            int id = tid + i * 128;
            int row = id >> 2, kc = (id & 3) * 4;
            unsigned dst = sptr(&as[row * ASTR + kc]);
            const float* src = A + (long long)(m0 + row) * K + k0 + kc;
            asm volatile("cp.async.cg.shared.global [%0], [%1], 16;" :: "r"(dst), "l"(src));
        }
#pragma unroll
        for (int i = 0; i < 4; i++) {
            int id = tid + i * 128;
            int row = id >> 5, nc = (id & 31) * 4;
            unsigned dst = sptr(&bs[row * BSTR + nc]);
            const float* src = W + (long long)(k0 + row) * ldw + n0 + nc;
            asm volatile("cp.async.cg.shared.global [%0], [%1], 16;" :: "r"(dst), "l"(src));
        }
    };

    int nk = K / 16;
    loadTiles(0, 0);
    asm volatile("cp.async.commit_group;");
    loadTiles(1, 1);
    asm volatile("cp.async.commit_group;");

    for (int kt = 0; kt < nk; kt++) {
        asm volatile("cp.async.wait_group 1;");
        __syncthreads();

        // issue next-tile DMA immediately: overlaps the whole compute phase.
        // stage (kt+2)%3 == (kt-1)%3; its readers finished before the barrier above.
        if (kt + 2 < nk) loadTiles(kt + 2, (kt + 2) % 3);
        asm volatile("cp.async.commit_group;");

        int cur = kt % 3;
        const float* as = As + cur * (BM * ASTR);
        const float* bs = Bs + cur * (16 * BSTR);

        // ---- load + convert ALL fragments (both kk phases) up front ----
        unsigned af[2][MI][4], bf[2][8][2];
#pragma unroll
        for (int kk = 0; kk < 2; kk++) {
#pragma unroll
            for (int mi = 0; mi < MI; mi++) {
                int r = wm + mi * 16 + g;
                af[kk][mi][0] = tf32_of(as[r * ASTR + kk * 8 + tig]);
                af[kk][mi][1] = tf32_of(as[(r + 8) * ASTR + kk * 8 + tig]);
                af[kk][mi][2] = tf32_of(as[r * ASTR + kk * 8 + tig + 4]);
                af[kk][mi][3] = tf32_of(as[(r + 8) * ASTR + kk * 8 + tig + 4]);
            }
#pragma unroll
            for (int nj = 0; nj < 8; nj++) {
                int col = wn + nj * 8 + g;
                bf[kk][nj][0] = tf32_of(bs[(kk * 8 + tig) * BSTR + col]);
                bf[kk][nj][1] = tf32_of(bs[(kk * 8 + tig + 4) * BSTR + col]);
            }
        }

        // ---- dense MMA burst: 2 * MI * 8 independent MMAs ----
#pragma unroll
        for (int kk = 0; kk < 2; kk++)
#pragma unroll
            for (int mi = 0; mi < MI; mi++)
#pragma unroll
                for (int nj = 0; nj < 8; nj++)
                    asm volatile(
                        "mma.sync.aligned.m16n8k8.row.col.f32.tf32.tf32.f32 "
                        "{%0,%1,%2,%3},{%4,%5,%6,%7},{%8,%9},{%0,%1,%2,%3};\n"
                        : "+f"(acc[mi][nj][0]), "+f"(acc[mi][nj][1]),
                          "+f"(acc[mi][nj][2]), "+f"(acc[mi][nj][3])
                        : "r"(af[kk][mi][0]), "r"(af[kk][mi][1]),
                          "r"(af[kk][mi][2]), "r"(af[kk][mi][3]),
                          "r"(bf[kk][nj][0]), "r"(bf[kk][nj][1]));
    }

    // ---- epilogue ----
#pragma unroll
    for (int mi = 0; mi < MI; mi++) {
        int r0 = m0 + wm + mi * 16 + g;
#pragma unroll
        for (int nj = 0; nj < 8; nj++) {
            int col = n0 + wn + nj * 8 + 2 * tig;
#pragma unroll
            for (int half = 0; half < 2; half++) {
                int rr = r0 + half * 8;
#pragma unroll
                for (int jj = 0; jj < 2; jj++) {
                    int cc = col + jj;
                    if (cc < N) {
                        float v = acc[mi][nj][half * 2 + jj];
                        if (epi != 3) v += bias[cc];
                        if (epi == 1) v = gelu_f(v);
                        long long o = (long long)rr * N + cc;
                        if (epi == 2) v += out[o];
                        out[o] = v;
                    }
                }
            }
        }
    }
}

// ---------------- tiled fp32 flash attention ----------------
// Block: 64 queries x 1 head, kv tiles of 64. 256 threads = 16(ty: 4 q) x 16(tx).
__global__ void __launch_bounds__(256)
fattn_kernel(const float* __restrict__ qkv, float* __restrict__ out) {
    extern __shared__ float sm[];
    float (*sQt)[68] = (float(*)[68])(sm);              // [d][q]
    float (*sKt)[68] = (float(*)[68])(sm + 64 * 68);    // [d][kv]
    float (*sV)[68]  = (float(*)[68])(sm + 2 * 64 * 68);// [kv][d]
    float (*sP)[68]  = (float(*)[68])(sm + 3 * 64 * 68);// [q][kv]

    int tid = threadIdx.x;
    int tx = tid & 15, ty = tid >> 4;
    int qt = (int)gridDim.x - 1 - (int)blockIdx.x;  // heavy tiles first
    int h = blockIdx.y, b = blockIdx.z;
    int q0 = qt * 64;

    {
        int r = tid >> 4;
        int c4 = (tid & 15) * 4;
#pragma unroll
        for (int rr = 0; rr < 64; rr += 16) {
            const float* qrow = qkv + (long long)(b * Tlen + q0 + r + rr) * C3 + h * HD;
            float4 v = *(const float4*)(qrow + c4);
            sQt[c4 + 0][r + rr] = v.x;
            sQt[c4 + 1][r + rr] = v.y;
            sQt[c4 + 2][r + rr] = v.z;
            sQt[c4 + 3][r + rr] = v.w;
        }
    }

    float O[4][4] = {};
    float m[4], l[4];
#pragma unroll
    for (int i = 0; i < 4; i++) { m[i] = -INFINITY; l[i] = 0.f; }

    const float scale = 0.125f;
    int ntiles = qt + 1;

    for (int kt = 0; kt < ntiles; kt++) {
        int kv0 = kt * 64;
        __syncthreads();
        {
            int r = tid >> 4;
            int c4 = (tid & 15) * 4;
#pragma unroll
            for (int rr0 = 0; rr0 < 64; rr0 += 16) {
                int rr = r + rr0;
                const float* krow = qkv + (long long)(b * Tlen + kv0 + rr) * C3 + C + h * HD;
                float4 kv4 = *(const float4*)(krow + c4);
                sKt[c4 + 0][rr] = kv4.x;
                sKt[c4 + 1][rr] = kv4.y;
                sKt[c4 + 2][rr] = kv4.z;
                sKt[c4 + 3][rr] = kv4.w;
                const float* vrow = qkv + (long long)(b * Tlen + kv0 + rr) * C3 + 2 * C + h * HD;
                *(float4*)&sV[rr][c4] = *(const float4*)(vrow + c4);
            }
        }
        __syncthreads();

        float s[4][4] = {};
#pragma unroll 16
        for (int kk = 0; kk < 64; kk++) {
            float4 a = *(const float4*)&sQt[kk][ty * 4];
            float4 bv = *(const float4*)&sKt[kk][tx * 4];
            s[0][0] += a.x * bv.x; s[0][1] += a.x * bv.y; s[0][2] += a.x * bv.z; s[0][3] += a.x * bv.w;
            s[1][0] += a.y * bv.x; s[1][1] += a.y * bv.y; s[1][2] += a.y * bv.z; s[1][3] += a.y * bv.w;
            s[2][0] += a.z * bv.x; s[2][1] += a.z * bv.y; s[2][2] += a.z * bv.z; s[2][3] += a.z * bv.w;
            s[3][0] += a.w * bv.x; s[3][1] += a.w * bv.y; s[3][2] += a.w * bv.z; s[3][3] += a.w * bv.w;
        }
#pragma unroll
        for (int i = 0; i < 4; i++)
#pragma unroll
            for (int j = 0; j < 4; j++) s[i][j] *= scale;

        if (kt == qt) {
#pragma unroll
            for (int i = 0; i < 4; i++) {
                int qg = q0 + ty * 4 + i;
#pragma unroll
                for (int j = 0; j < 4; j++)
                    if (kv0 + tx * 4 + j > qg) s[i][j] = -INFINITY;
            }
        }

#pragma unroll
        for (int i = 0; i < 4; i++) {
            float rm = fmaxf(fmaxf(s[i][0], s[i][1]), fmaxf(s[i][2], s[i][3]));
#pragma unroll
            for (int off = 1; off < 16; off <<= 1)
                rm = fmaxf(rm, __shfl_xor_sync(0xFFFFFFFFu, rm, off));
            float mn = fmaxf(m[i], rm);
            float cs = __expf(m[i] - mn);
            float p0 = __expf(s[i][0] - mn);
            float p1 = __expf(s[i][1] - mn);
            float p2 = __expf(s[i][2] - mn);
            float p3 = __expf(s[i][3] - mn);
            float rs = (p0 + p1) + (p2 + p3);
#pragma unroll
            for (int off = 1; off < 16; off <<= 1)
                rs += __shfl_xor_sync(0xFFFFFFFFu, rs, off);
            l[i] = l[i] * cs + rs;
            m[i] = mn;
            O[i][0] *= cs; O[i][1] *= cs; O[i][2] *= cs; O[i][3] *= cs;
            sP[ty * 4 + i][tx * 4 + 0] = p0;
            sP[ty * 4 + i][tx * 4 + 1] = p1;
            sP[ty * 4 + i][tx * 4 + 2] = p2;
            sP[ty * 4 + i][tx * 4 + 3] = p3;
        }
        __syncthreads();

#pragma unroll 8
        for (int kv = 0; kv < 64; kv++) {
            float4 v = *(const float4*)&sV[kv][tx * 4];
            float p0 = sP[ty * 4 + 0][kv];
            float p1 = sP[ty * 4 + 1][kv];
            float p2 = sP[ty * 4 + 2][kv];
            float p3 = sP[ty * 4 + 3][kv];
            O[0][0] += p0 * v.x; O[0][1] += p0 * v.y; O[0][2] += p0 * v.z; O[0][3] += p0 * v.w;
            O[1][0] += p1 * v.x; O[1][1] += p1 * v.y; O[1][2] += p1 * v.z; O[1][3] += p1 * v.w;
            O[2][0] += p2 * v.x; O[2][1] += p2 * v.y; O[2][2] += p2 * v.z; O[2][3] += p2 * v.w;
            O[3][0] += p3 * v.x; O[3][1] += p3 * v.y; O[3][2] += p3 * v.z; O[3][3] += p3 * v.w;
        }
    }

#pragma unroll
    for (int i = 0; i < 4; i++) {
        float inv = 1.f / l[i];
        float4 o4;
        o4.x = O[i][0] * inv; o4.y = O[i][1] * inv;
        o4.z = O[i][2] * inv; o4.w = O[i][3] * inv;
        float* o = out + (long long)(b * Tlen + q0 + ty * 4 + i) * C + h * HD + tx * 4;
        *(float4*)o = o4;
    }
}

// ---------------- driver ----------------
#define GEMM_SMEM(BM) (3 * ((BM) * ASTR + 16 * BSTR) * (int)sizeof(float))
#define ATTN_SMEM (4 * 64 * 68 * (int)sizeof(float))

extern "C" void kernel_launch(void* const* d_in, const int* in_sizes, int n_in,
                              void* d_out, int out_size) {
    const int*   idx      = (const int*)  d_in[0];
    const float* wte      = (const float*)d_in[1];
    const float* wpe      = (const float*)d_in[2];
    const float* ln1_w    = (const float*)d_in[3];
    const float* ln1_b    = (const float*)d_in[4];
    const float* attn_w   = (const float*)d_in[5];
    const float* attn_b   = (const float*)d_in[6];
    const float* proj_w   = (const float*)d_in[7];
    const float* proj_b   = (const float*)d_in[8];
    const float* ln2_w    = (const float*)d_in[9];
    const float* ln2_b    = (const float*)d_in[10];
    const float* fc_w     = (const float*)d_in[11];
    const float* fc_b     = (const float*)d_in[12];
    const float* fcproj_w = (const float*)d_in[13];
    const float* fcproj_b = (const float*)d_in[14];
    const float* lnf_w    = (const float*)d_in[15];
    const float* lnf_b    = (const float*)d_in[16];
    const float* lm_head  = (const float*)d_in[17];
    float* out = (float*)d_out;

    float *x, *ln, *qkv, *atty, *hbuf, *wpad;
    cudaGetSymbolAddress((void**)&x,    g_x);
    cudaGetSymbolAddress((void**)&ln,   g_ln);
    cudaGetSymbolAddress((void**)&qkv,  g_qkv);
    cudaGetSymbolAddress((void**)&atty, g_atty);
    cudaGetSymbolAddress((void**)&hbuf, g_h);
    cudaGetSymbolAddress((void**)&wpad, g_wpad);

    cudaFuncSetAttribute(tgemm_kernel<128>,
                         cudaFuncAttributeMaxDynamicSharedMemorySize, GEMM_SMEM(128));
    cudaFuncSetAttribute(tgemm_kernel<64>,
                         cudaFuncAttributeMaxDynamicSharedMemorySize, GEMM_SMEM(64));
    cudaFuncSetAttribute(fattn_kernel,
                         cudaFuncAttributeMaxDynamicSharedMemorySize, ATTN_SMEM);

    embed_kernel<<<BT, 256>>>(idx, wte, wpe, x);
    padw_kernel<<<dim3((VP + 255) / 256, C), 256>>>(lm_head, wpad);

    for (int l = 0; l < NL; l++) {
        ln_kernel<<<BT, 256>>>(x, ln1_w + l * C, ln1_b + l * C, ln);
        tgemm_kernel<128><<<dim3(C3 / 128, BT / 128), 128, GEMM_SMEM(128)>>>(
            ln, attn_w + (long long)l * C * C3, attn_b + l * C3, qkv, BT, C3, C, C3, 0);
        fattn_kernel<<<dim3(Tlen / 64, H, Bsz), 256, ATTN_SMEM>>>(qkv, atty);
        tgemm_kernel<64><<<dim3(C / 128, BT / 64), 128, GEMM_SMEM(64)>>>(
            atty, proj_w + (long long)l * C * C, proj_b + l * C, x, BT, C, C, C, 2);
        ln_kernel<<<BT, 256>>>(x, ln2_w + l * C, ln2_b + l * C, ln);
        tgemm_kernel<128><<<dim3(C4 / 128, BT / 128), 128, GEMM_SMEM(128)>>>(
            ln, fc_w + (long long)l * C * C4, fc_b + l * C4, hbuf, BT, C4, C, C4, 1);
        tgemm_kernel<64><<<dim3(C / 128, BT / 64), 128, GEMM_SMEM(64)>>>(
            hbuf, fcproj_w + (long long)l * C4 * C, fcproj_b + l * C, x, BT, C, C4, C, 2);
    }

    ln_kernel<<<BT, 256>>>(x, lnf_w, lnf_b, ln);
    tgemm_kernel<128><<<dim3(VP / 128, BT / 128), 128, GEMM_SMEM(128)>>>(
        ln, wpad, (const float*)nullptr, out, BT, V, C, VP, 3);
}

// round 8
// speedup vs baseline: 1.0381x; 1.0361x over previous
#include <cuda_runtime.h>
#include <math.h>

// GPT-2 small forward: tf32 tensor GEMMs with pre-rounded (tf32-grid) inputs in gmem
// -> zero CVT in the GEMM hot loop. Tiled fp32 flash attention.
// B=2, T=1024, C=768, H=12, HD=64, L=12, V=50257.

#define Bsz 2
#define Tlen 1024
#define BT (Bsz * Tlen)      // 2048
#define C 768
#define H 12
#define HD 64
#define NL 12
#define V 50257
#define VP 50304             // V padded to multiple of 128
#define C3 (3 * C)           // 2304
#define C4 (4 * C)           // 3072
#define EPS 1e-5f

// ---------------- scratch ----------------
__device__ float g_x[BT * C];
__device__ float g_ln[BT * C];      // tf32-rounded LN output
__device__ float g_qkv[BT * C3];
__device__ float g_atty[BT * C];    // tf32-rounded attention output
__device__ float g_h[BT * C4];      // tf32-rounded gelu output
__device__ float g_wpad[(long long)C * VP];       // rounded + padded lm_head
__device__ float g_wqkv[(long long)NL * C * C3];  // rounded attn_w
__device__ float g_wproj[(long long)NL * C * C];  // rounded proj_w
__device__ float g_wfc[(long long)NL * C * C4];   // rounded fc_w
__device__ float g_wfp[(long long)NL * C4 * C];   // rounded fcproj_w

// ---------------- helpers ----------------
__device__ __forceinline__ float gelu_f(float x) {
    float x3 = x * x * x;
    return 0.5f * x * (1.f + tanhf(0.7978845608028654f * (x + 0.044715f * x3)));
}

__device__ __forceinline__ unsigned tf32_of(float f) {
    unsigned u;
    asm("cvt.rna.tf32.f32 %0, %1;" : "=r"(u) : "f"(f));
    return u;
}
__device__ __forceinline__ float tf32r(float f) { return __uint_as_float(tf32_of(f)); }

__device__ __forceinline__ unsigned sptr(const void* p) {
    return (unsigned)__cvta_generic_to_shared(p);
}

// ---------------- embedding ----------------
__global__ void embed_kernel(const int* __restrict__ idx,
                             const float* __restrict__ wte,
                             const float* __restrict__ wpe,
                             float* __restrict__ out) {
    int row = blockIdx.x;
    int tpos = row % Tlen;
    int tok = idx[row];
    const float* we = wte + (long long)tok * C;
    const float* pe = wpe + (long long)tpos * C;
    float* o = out + (long long)row * C;
    for (int c = threadIdx.x; c < C; c += blockDim.x)
        o[c] = we[c] + pe[c];
}

// ---------------- weight pre-rounding (vectorized, n divisible by 4) ----------------
__global__ void cvtw_kernel(const float* __restrict__ w, float* __restrict__ o, long long n4) {
    long long i = (long long)blockIdx.x * blockDim.x + threadIdx.x;
    if (i < n4) {
        float4 v = ((const float4*)w)[i];
        v.x = tf32r(v.x); v.y = tf32r(v.y); v.z = tf32r(v.z); v.w = tf32r(v.w);
        ((float4*)o)[i] = v;
    }
}

// ---------------- lm_head pad + round ----------------
__global__ void padw_kernel(const float* __restrict__ w, float* __restrict__ wp) {
    int k = blockIdx.y;
    int n = blockIdx.x * blockDim.x + threadIdx.x;
    if (n < VP)
        wp[(long long)k * VP + n] = (n < V) ? tf32r(w[(long long)k * V + n]) : 0.f;
}

// ---------------- layernorm (tf32-rounded output) ----------------
__global__ void ln_kernel(const float* __restrict__ x,
                          const float* __restrict__ w,
                          const float* __restrict__ b,
                          float* __restrict__ out) {
    __shared__ float red[256];
    __shared__ float red2[256];
    int row = blockIdx.x;
    const float* xr = x + (long long)row * C;
    float s = 0.f, sq = 0.f;
    for (int c = threadIdx.x; c < C; c += blockDim.x) {
        float v = xr[c];
        s += v; sq += v * v;
    }
    red[threadIdx.x] = s; red2[threadIdx.x] = sq;
    __syncthreads();
    for (int off = 128; off > 0; off >>= 1) {
        if (threadIdx.x < off) {
            red[threadIdx.x] += red[threadIdx.x + off];
            red2[threadIdx.x] += red2[threadIdx.x + off];
        }
        __syncthreads();
    }
    float mean = red[0] / C;
    float var = red2[0] / C - mean * mean;
    float rstd = rsqrtf(var + EPS);
    float* o = out + (long long)row * C;
    for (int c = threadIdx.x; c < C; c += blockDim.x)
        o[c] = tf32r((xr[c] - mean) * rstd * w[c] + b[c]);
}

// ---------------- 3-stage cp.async tf32 GEMM (no CVT in loop) ----------------
// out[M,N] = A[M,K] @ W[K,N] (W row stride ldw); epi: 0=+bias, 1=gelu->round, 2=+residual, 3=none
// 128 threads (4 warps 2x2), tile BM x 128, warp tile (BM/2) x 64, K-tile 16, 3 stages.
// A and W must already be on the tf32 grid (rounded in gmem).
#define ASTR 20      // 16 + 4 pad
#define BSTR 136     // 128 + 8 pad

template<int BM>
__global__ void __launch_bounds__(128)
tgemm_kernel(const float* __restrict__ A, const float* __restrict__ W,
             const float* __restrict__ bias, float* __restrict__ out,
             int M, int N, int K, int ldw, int epi) {
    constexpr int MI = BM / 32;
    extern __shared__ float sm[];
    float* As = sm;                       // 3 stages of BM*ASTR
    float* Bs = sm + 3 * BM * ASTR;       // 3 stages of 16*BSTR

    int tid = threadIdx.x;
    int w = tid >> 5, lane = tid & 31;
    int g = lane >> 2, tig = lane & 3;
    int wm = (w & 1) * (BM / 2);
    int wn = (w >> 1) * 64;
    int m0 = blockIdx.y * BM;
    int n0 = blockIdx.x * 128;

    float acc[MI][8][4];
#pragma unroll
    for (int mi = 0; mi < MI; mi++)
#pragma unroll
        for (int nj = 0; nj < 8; nj++)
#pragma unroll
            for (int r = 0; r < 4; r++) acc[mi][nj][r] = 0.f;

    auto loadTiles = [&](int kt, int s) {
        int k0 = kt * 16;
        float* as = As + s * (BM * ASTR);
        float* bs = Bs + s * (16 * BSTR);
#pragma unroll
        for (int i = 0; i < BM / 32; i++) {
            int id = tid + i * 128;
            int row = id >> 2, kc = (id & 3) * 4;
            unsigned dst = sptr(&as[row * ASTR + kc]);
            const float* src = A + (long long)(m0 + row) * K + k0 + kc;
            asm volatile("cp.async.cg.shared.global [%0], [%1], 16;" :: "r"(dst), "l"(src));
        }
#pragma unroll
        for (int i = 0; i < 4; i++) {
            int id = tid + i * 128;
            int row = id >> 5, nc = (id & 31) * 4;
            unsigned dst = sptr(&bs[row * BSTR + nc]);
            const float* src = W + (long long)(k0 + row) * ldw + n0 + nc;
            asm volatile("cp.async.cg.shared.global [%0], [%1], 16;" :: "r"(dst), "l"(src));
        }
    };

    int nk = K / 16;
    loadTiles(0, 0);
    asm volatile("cp.async.commit_group;");
    loadTiles(1, 1);
    asm volatile("cp.async.commit_group;");

    for (int kt = 0; kt < nk; kt++) {
        asm volatile("cp.async.wait_group 1;");
        __syncthreads();

        if (kt + 2 < nk) loadTiles(kt + 2, (kt + 2) % 3);
        asm volatile("cp.async.commit_group;");

        int cur = kt % 3;
        const float* as = As + cur * (BM * ASTR);
        const float* bs = Bs + cur * (16 * BSTR);

#pragma unroll
        for (int kk = 0; kk < 2; kk++) {
            unsigned af[MI][4], bf[8][2];
#pragma unroll
            for (int mi = 0; mi < MI; mi++) {
                int r = wm + mi * 16 + g;
                af[mi][0] = __float_as_uint(as[r * ASTR + kk * 8 + tig]);
                af[mi][1] = __float_as_uint(as[(r + 8) * ASTR + kk * 8 + tig]);
                af[mi][2] = __float_as_uint(as[r * ASTR + kk * 8 + tig + 4]);
                af[mi][3] = __float_as_uint(as[(r + 8) * ASTR + kk * 8 + tig + 4]);
            }
#pragma unroll
            for (int nj = 0; nj < 8; nj++) {
                int col = wn + nj * 8 + g;
                bf[nj][0] = __float_as_uint(bs[(kk * 8 + tig) * BSTR + col]);
                bf[nj][1] = __float_as_uint(bs[(kk * 8 + tig + 4) * BSTR + col]);
            }
#pragma unroll
            for (int mi = 0; mi < MI; mi++)
#pragma unroll
                for (int nj = 0; nj < 8; nj++)
                    asm volatile(
                        "mma.sync.aligned.m16n8k8.row.col.f32.tf32.tf32.f32 "
                        "{%0,%1,%2,%3},{%4,%5,%6,%7},{%8,%9},{%0,%1,%2,%3};\n"
                        : "+f"(acc[mi][nj][0]), "+f"(acc[mi][nj][1]),
                          "+f"(acc[mi][nj][2]), "+f"(acc[mi][nj][3])
                        : "r"(af[mi][0]), "r"(af[mi][1]), "r"(af[mi][2]), "r"(af[mi][3]),
                          "r"(bf[nj][0]), "r"(bf[nj][1]));
        }
    }

    // ---- epilogue ----
#pragma unroll
    for (int mi = 0; mi < MI; mi++) {
        int r0 = m0 + wm + mi * 16 + g;
#pragma unroll
        for (int nj = 0; nj < 8; nj++) {
            int col = n0 + wn + nj * 8 + 2 * tig;
#pragma unroll
            for (int half = 0; half < 2; half++) {
                int rr = r0 + half * 8;
#pragma unroll
                for (int jj = 0; jj < 2; jj++) {
                    int cc = col + jj;
                    if (cc < N) {
                        float v = acc[mi][nj][half * 2 + jj];
                        if (epi != 3) v += bias[cc];
                        if (epi == 1) v = tf32r(gelu_f(v));   // feeds next GEMM's A
                        long long o = (long long)rr * N + cc;
                        if (epi == 2) v += out[o];
                        out[o] = v;
                    }
                }
            }
        }
    }
}

// ---------------- tiled fp32 flash attention (tf32-rounded output) ----------------
__global__ void __launch_bounds__(256)
fattn_kernel(const float* __restrict__ qkv, float* __restrict__ out) {
    extern __shared__ float sm[];
    float (*sQt)[68] = (float(*)[68])(sm);              // [d][q]
    float (*sKt)[68] = (float(*)[68])(sm + 64 * 68);    // [d][kv]
    float (*sV)[68]  = (float(*)[68])(sm + 2 * 64 * 68);// [kv][d]
    float (*sP)[68]  = (float(*)[68])(sm + 3 * 64 * 68);// [q][kv]

    int tid = threadIdx.x;
    int tx = tid & 15, ty = tid >> 4;
    int qt = (int)gridDim.x - 1 - (int)blockIdx.x;  // heavy tiles first
    int h = blockIdx.y, b = blockIdx.z;
    int q0 = qt * 64;

    {
        int r = tid >> 4;
        int c4 = (tid & 15) * 4;
#pragma unroll
        for (int rr = 0; rr < 64; rr += 16) {
            const float* qrow = qkv + (long long)(b * Tlen + q0 + r + rr) * C3 + h * HD;
            float4 v = *(const float4*)(qrow + c4);
            sQt[c4 + 0][r + rr] = v.x;
            sQt[c4 + 1][r + rr] = v.y;
            sQt[c4 + 2][r + rr] = v.z;
            sQt[c4 + 3][r + rr] = v.w;
        }
    }

    float O[4][4] = {};
    float m[4], l[4];
#pragma unroll
    for (int i = 0; i < 4; i++) { m[i] = -INFINITY; l[i] = 0.f; }

    const float scale = 0.125f;
    int ntiles = qt + 1;

    for (int kt = 0; kt < ntiles; kt++) {
        int kv0 = kt * 64;
        __syncthreads();
        {
            int r = tid >> 4;
            int c4 = (tid & 15) * 4;
#pragma unroll
            for (int rr0 = 0; rr0 < 64; rr0 += 16) {
                int rr = r + rr0;
                const float* krow = qkv + (long long)(b * Tlen + kv0 + rr) * C3 + C + h * HD;
                float4 kv4 = *(const float4*)(krow + c4);
                sKt[c4 + 0][rr] = kv4.x;
                sKt[c4 + 1][rr] = kv4.y;
                sKt[c4 + 2][rr] = kv4.z;
                sKt[c4 + 3][rr] = kv4.w;
                const float* vrow = qkv + (long long)(b * Tlen + kv0 + rr) * C3 + 2 * C + h * HD;
                *(float4*)&sV[rr][c4] = *(const float4*)(vrow + c4);
            }
        }
        __syncthreads();

        float s[4][4] = {};
#pragma unroll 16
        for (int kk = 0; kk < 64; kk++) {
            float4 a = *(const float4*)&sQt[kk][ty * 4];
            float4 bv = *(const float4*)&sKt[kk][tx * 4];
            s[0][0] += a.x * bv.x; s[0][1] += a.x * bv.y; s[0][2] += a.x * bv.z; s[0][3] += a.x * bv.w;
            s[1][0] += a.y * bv.x; s[1][1] += a.y * bv.y; s[1][2] += a.y * bv.z; s[1][3] += a.y * bv.w;
            s[2][0] += a.z * bv.x; s[2][1] += a.z * bv.y; s[2][2] += a.z * bv.z; s[2][3] += a.z * bv.w;
            s[3][0] += a.w * bv.x; s[3][1] += a.w * bv.y; s[3][2] += a.w * bv.z; s[3][3] += a.w * bv.w;
        }
#pragma unroll
        for (int i = 0; i < 4; i++)
#pragma unroll
            for (int j = 0; j < 4; j++) s[i][j] *= scale;

        if (kt == qt) {
#pragma unroll
            for (int i = 0; i < 4; i++) {
                int qg = q0 + ty * 4 + i;
#pragma unroll
                for (int j = 0; j < 4; j++)
                    if (kv0 + tx * 4 + j > qg) s[i][j] = -INFINITY;
            }
        }

#pragma unroll
        for (int i = 0; i < 4; i++) {
            float rm = fmaxf(fmaxf(s[i][0], s[i][1]), fmaxf(s[i][2], s[i][3]));
#pragma unroll
            for (int off = 1; off < 16; off <<= 1)
                rm = fmaxf(rm, __shfl_xor_sync(0xFFFFFFFFu, rm, off));
            float mn = fmaxf(m[i], rm);
            float cs = __expf(m[i] - mn);
            float p0 = __expf(s[i][0] - mn);
            float p1 = __expf(s[i][1] - mn);
            float p2 = __expf(s[i][2] - mn);
            float p3 = __expf(s[i][3] - mn);
            float rs = (p0 + p1) + (p2 + p3);
#pragma unroll
            for (int off = 1; off < 16; off <<= 1)
                rs += __shfl_xor_sync(0xFFFFFFFFu, rs, off);
            l[i] = l[i] * cs + rs;
            m[i] = mn;
            O[i][0] *= cs; O[i][1] *= cs; O[i][2] *= cs; O[i][3] *= cs;
            sP[ty * 4 + i][tx * 4 + 0] = p0;
            sP[ty * 4 + i][tx * 4 + 1] = p1;
            sP[ty * 4 + i][tx * 4 + 2] = p2;
            sP[ty * 4 + i][tx * 4 + 3] = p3;
        }
        __syncthreads();

#pragma unroll 8
        for (int kv = 0; kv < 64; kv++) {
            float4 v = *(const float4*)&sV[kv][tx * 4];
            float p0 = sP[ty * 4 + 0][kv];
            float p1 = sP[ty * 4 + 1][kv];
            float p2 = sP[ty * 4 + 2][kv];
            float p3 = sP[ty * 4 + 3][kv];
            O[0][0] += p0 * v.x; O[0][1] += p0 * v.y; O[0][2] += p0 * v.z; O[0][3] += p0 * v.w;
            O[1][0] += p1 * v.x; O[1][1] += p1 * v.y; O[1][2] += p1 * v.z; O[1][3] += p1 * v.w;
            O[2][0] += p2 * v.x; O[2][1] += p2 * v.y; O[2][2] += p2 * v.z; O[2][3] += p2 * v.w;
            O[3][0] += p3 * v.x; O[3][1] += p3 * v.y; O[3][2] += p3 * v.z; O[3][3] += p3 * v.w;
        }
    }

#pragma unroll
    for (int i = 0; i < 4; i++) {
        float inv = 1.f / l[i];
        float4 o4;
        o4.x = tf32r(O[i][0] * inv); o4.y = tf32r(O[i][1] * inv);
        o4.z = tf32r(O[i][2] * inv); o4.w = tf32r(O[i][3] * inv);
        float* o = out + (long long)(b * Tlen + q0 + ty * 4 + i) * C + h * HD + tx * 4;
        *(float4*)o = o4;
    }
}

// ---------------- driver ----------------
#define GEMM_SMEM(BM) (3 * ((BM) * ASTR + 16 * BSTR) * (int)sizeof(float))
#define ATTN_SMEM (4 * 64 * 68 * (int)sizeof(float))

extern "C" void kernel_launch(void* const* d_in, const int* in_sizes, int n_in,
                              void* d_out, int out_size) {
    const int*   idx      = (const int*)  d_in[0];
    const float* wte      = (const float*)d_in[1];
    const float* wpe      = (const float*)d_in[2];
    const float* ln1_w    = (const float*)d_in[3];
    const float* ln1_b    = (const float*)d_in[4];
    const float* attn_w   = (const float*)d_in[5];
    const float* attn_b   = (const float*)d_in[6];
    const float* proj_w   = (const float*)d_in[7];
    const float* proj_b   = (const float*)d_in[8];
    const float* ln2_w    = (const float*)d_in[9];
    const float* ln2_b    = (const float*)d_in[10];
    const float* fc_w     = (const float*)d_in[11];
    const float* fc_b     = (const float*)d_in[12];
    const float* fcproj_w = (const float*)d_in[13];
    const float* fcproj_b = (const float*)d_in[14];
    const float* lnf_w    = (const float*)d_in[15];
    const float* lnf_b    = (const float*)d_in[16];
    const float* lm_head  = (const float*)d_in[17];
    float* out = (float*)d_out;

    float *x, *ln, *qkv, *atty, *hbuf, *wpad, *wq, *wp, *wf, *wfp;
    cudaGetSymbolAddress((void**)&x,    g_x);
    cudaGetSymbolAddress((void**)&ln,   g_ln);
    cudaGetSymbolAddress((void**)&qkv,  g_qkv);
    cudaGetSymbolAddress((void**)&atty, g_atty);
    cudaGetSymbolAddress((void**)&hbuf, g_h);
    cudaGetSymbolAddress((void**)&wpad, g_wpad);
    cudaGetSymbolAddress((void**)&wq,   g_wqkv);
    cudaGetSymbolAddress((void**)&wp,   g_wproj);
    cudaGetSymbolAddress((void**)&wf,   g_wfc);
    cudaGetSymbolAddress((void**)&wfp,  g_wfp);

    cudaFuncSetAttribute(tgemm_kernel<128>,
                         cudaFuncAttributeMaxDynamicSharedMemorySize, GEMM_SMEM(128));
    cudaFuncSetAttribute(tgemm_kernel<64>,
                         cudaFuncAttributeMaxDynamicSharedMemorySize, GEMM_SMEM(64));
    cudaFuncSetAttribute(fattn_kernel,
                         cudaFuncAttributeMaxDynamicSharedMemorySize, ATTN_SMEM);

    // one-time per-launch weight rounding
    {
        long long n4;
        n4 = (long long)NL * C * C3 / 4;
        cvtw_kernel<<<(int)((n4 + 255) / 256), 256>>>(attn_w, wq, n4);
        n4 = (long long)NL * C * C / 4;
        cvtw_kernel<<<(int)((n4 + 255) / 256), 256>>>(proj_w, wp, n4);
        n4 = (long long)NL * C * C4 / 4;
        cvtw_kernel<<<(int)((n4 + 255) / 256), 256>>>(fc_w, wf, n4);
        n4 = (long long)NL * C4 * C / 4;
        cvtw_kernel<<<(int)((n4 + 255) / 256), 256>>>(fcproj_w, wfp, n4);
    }
    padw_kernel<<<dim3((VP + 255) / 256, C), 256>>>(lm_head, wpad);
    embed_kernel<<<BT, 256>>>(idx, wte, wpe, x);

    for (int l = 0; l < NL; l++) {
        ln_kernel<<<BT, 256>>>(x, ln1_w + l * C, ln1_b + l * C, ln);
        tgemm_kernel<128><<<dim3(C3 / 128, BT / 128), 128, GEMM_SMEM(128)>>>(
            ln, wq + (long long)l * C * C3, attn_b + l * C3, qkv, BT, C3, C, C3, 0);
        fattn_kernel<<<dim3(Tlen / 64, H, Bsz), 256, ATTN_SMEM>>>(qkv, atty);
        tgemm_kernel<64><<<dim3(C / 128, BT / 64), 128, GEMM_SMEM(64)>>>(
            atty, wp + (long long)l * C * C, proj_b + l * C, x, BT, C, C, C, 2);
        ln_kernel<<<BT, 256>>>(x, ln2_w + l * C, ln2_b + l * C, ln);
        tgemm_kernel<128><<<dim3(C4 / 128, BT / 128), 128, GEMM_SMEM(128)>>>(
            ln, wf + (long long)l * C * C4, fc_b + l * C4, hbuf, BT, C4, C, C4, 1);
        tgemm_kernel<64><<<dim3(C / 128, BT / 64), 128, GEMM_SMEM(64)>>>(
            hbuf, wfp + (long long)l * C4 * C, fcproj_b + l * C, x, BT, C, C4, C, 2);
    }

    ln_kernel<<<BT, 256>>>(x, lnf_w, lnf_b, ln);
    tgemm_kernel<128><<<dim3(VP / 128, BT / 128), 128, GEMM_SMEM(128)>>>(
        ln, wpad, (const float*)nullptr, out, BT, V, C, VP, 3);
}

// round 10
// speedup vs baseline: 1.0826x; 1.0429x over previous
#include <cuda_runtime.h>
#include <math.h>

// GPT-2 small forward: tf32 mma.sync GEMMs (pre-rounded operands, 8-warp blocks for
// latency coverage) + tiled fp32 flash attention.
// B=2, T=1024, C=768, H=12, HD=64, L=12, V=50257.

#define Bsz 2
#define Tlen 1024
#define BT (Bsz * Tlen)      // 2048
#define C 768
#define H 12
#define HD 64
#define NL 12
#define V 50257
#define VP 50304             // V padded to multiple of 128
#define C3 (3 * C)           // 2304
#define C4 (4 * C)           // 3072
#define EPS 1e-5f

// ---------------- scratch ----------------
__device__ float g_x[BT * C];
__device__ float g_ln[BT * C];      // tf32-rounded LN output
__device__ float g_qkv[BT * C3];
__device__ float g_atty[BT * C];    // tf32-rounded attention output
__device__ float g_h[BT * C4];      // tf32-rounded gelu output
__device__ float g_wpad[(long long)C * VP];       // rounded + padded lm_head
__device__ float g_wqkv[(long long)NL * C * C3];  // rounded attn_w
__device__ float g_wproj[(long long)NL * C * C];  // rounded proj_w
__device__ float g_wfc[(long long)NL * C * C4];   // rounded fc_w
__device__ float g_wfp[(long long)NL * C4 * C];   // rounded fcproj_w

// ---------------- helpers ----------------
__device__ __forceinline__ float gelu_f(float x) {
    float x3 = x * x * x;
    return 0.5f * x * (1.f + tanhf(0.7978845608028654f * (x + 0.044715f * x3)));
}

__device__ __forceinline__ unsigned tf32_of(float f) {
    unsigned u;
    asm("cvt.rna.tf32.f32 %0, %1;" : "=r"(u) : "f"(f));
    return u;
}
__device__ __forceinline__ float tf32r(float f) { return __uint_as_float(tf32_of(f)); }

__device__ __forceinline__ unsigned sptr(const void* p) {
    return (unsigned)__cvta_generic_to_shared(p);
}

// ---------------- embedding ----------------
__global__ void embed_kernel(const int* __restrict__ idx,
                             const float* __restrict__ wte,
                             const float* __restrict__ wpe,
                             float* __restrict__ out) {
    int row = blockIdx.x;
    int tpos = row % Tlen;
    int tok = idx[row];
    const float* we = wte + (long long)tok * C;
    const float* pe = wpe + (long long)tpos * C;
    float* o = out + (long long)row * C;
    for (int c = threadIdx.x; c < C; c += blockDim.x)
        o[c] = we[c] + pe[c];
}

// ---------------- weight pre-rounding ----------------
__global__ void cvtw_kernel(const float* __restrict__ w, float* __restrict__ o, long long n4) {
    long long i = (long long)blockIdx.x * blockDim.x + threadIdx.x;
    if (i < n4) {
        float4 v = ((const float4*)w)[i];
        v.x = tf32r(v.x); v.y = tf32r(v.y); v.z = tf32r(v.z); v.w = tf32r(v.w);
        ((float4*)o)[i] = v;
    }
}

// ---------------- lm_head pad + round ----------------
__global__ void padw_kernel(const float* __restrict__ w, float* __restrict__ wp) {
    int k = blockIdx.y;
    int n = blockIdx.x * blockDim.x + threadIdx.x;
    if (n < VP)
        wp[(long long)k * VP + n] = (n < V) ? tf32r(w[(long long)k * V + n]) : 0.f;
}

// ---------------- layernorm (tf32-rounded output) ----------------
__global__ void ln_kernel(const float* __restrict__ x,
                          const float* __restrict__ w,
                          const float* __restrict__ b,
                          float* __restrict__ out) {
    __shared__ float red[256];
    __shared__ float red2[256];
    int row = blockIdx.x;
    const float* xr = x + (long long)row * C;
    float s = 0.f, sq = 0.f;
    for (int c = threadIdx.x; c < C; c += blockDim.x) {
        float v = xr[c];
        s += v; sq += v * v;
    }
    red[threadIdx.x] = s; red2[threadIdx.x] = sq;
    __syncthreads();
    for (int off = 128; off > 0; off >>= 1) {
        if (threadIdx.x < off) {
            red[threadIdx.x] += red[threadIdx.x + off];
            red2[threadIdx.x] += red2[threadIdx.x + off];
        }
        __syncthreads();
    }
    float mean = red[0] / C;
    float var = red2[0] / C - mean * mean;
    float rstd = rsqrtf(var + EPS);
    float* o = out + (long long)row * C;
    for (int c = threadIdx.x; c < C; c += blockDim.x)
        o[c] = tf32r((xr[c] - mean) * rstd * w[c] + b[c]);
}

// ---------------- 3-stage cp.async tf32 GEMM, 256 threads / 8 warps ----------------
// out[M,N] = A[M,K] @ W[K,N] (W row stride ldw); epi: 0=+bias, 1=gelu->round, 2=+residual, 3=none
// Tile BM x 128; 8 warps (2 in M x 4 in N), warp tile (BM/2) x 32; K-tile 16; 3 stages.
// A and W pre-rounded to the tf32 grid in gmem -> no CVT in the loop.
#define ASTR 20      // 16 + 4 pad
#define BSTR 136     // 128 + 8 pad

template<int BM>
__global__ void __launch_bounds__(256, 2)
tgemm_kernel(const float* __restrict__ A, const float* __restrict__ W,
             const float* __restrict__ bias, float* __restrict__ out,
             int M, int N, int K, int ldw, int epi) {
    constexpr int MI = BM / 32;           // m-fragments per warp
    extern __shared__ float sm[];
    float* As = sm;                       // 3 stages of BM*ASTR
    float* Bs = sm + 3 * BM * ASTR;       // 3 stages of 16*BSTR

    int tid = threadIdx.x;
    int w = tid >> 5, lane = tid & 31;
    int g = lane >> 2, tig = lane & 3;
    int wm = (w & 1) * (BM / 2);
    int wn = (w >> 1) * 32;
    int m0 = blockIdx.y * BM;
    int n0 = blockIdx.x * 128;

    float acc[MI][4][4];
#pragma unroll
    for (int mi = 0; mi < MI; mi++)
#pragma unroll
        for (int nj = 0; nj < 4; nj++)
#pragma unroll
            for (int r = 0; r < 4; r++) acc[mi][nj][r] = 0.f;

    auto loadTiles = [&](int kt, int s) {
        int k0 = kt * 16;
        float* as = As + s * (BM * ASTR);
        float* bs = Bs + s * (16 * BSTR);
        // A tile: BM x 16 floats, 16B chunks; BM/64 chunks per thread
#pragma unroll
        for (int i = 0; i < BM / 64; i++) {
            int id = tid + i * 256;
            int row = id >> 2, kc = (id & 3) * 4;
            unsigned dst = sptr(&as[row * ASTR + kc]);
            const float* src = A + (long long)(m0 + row) * K + k0 + kc;
            asm volatile("cp.async.cg.shared.global [%0], [%1], 16;" :: "r"(dst), "l"(src));
        }
        // B tile: 16 x 128 floats, 2 chunks per thread
#pragma unroll
        for (int i = 0; i < 2; i++) {
            int id = tid + i * 256;
            int row = id >> 5, nc = (id & 31) * 4;
            unsigned dst = sptr(&bs[row * BSTR + nc]);
            const float* src = W + (long long)(k0 + row) * ldw + n0 + nc;
            asm volatile("cp.async.cg.shared.global [%0], [%1], 16;" :: "r"(dst), "l"(src));
        }
    };

    int nk = K / 16;
    loadTiles(0, 0);
    asm volatile("cp.async.commit_group;");
    loadTiles(1, 1);
    asm volatile("cp.async.commit_group;");

    for (int kt = 0; kt < nk; kt++) {
        asm volatile("cp.async.wait_group 1;");
        __syncthreads();

        if (kt + 2 < nk) loadTiles(kt + 2, (kt + 2) % 3);
        asm volatile("cp.async.commit_group;");

        int cur = kt % 3;
        const float* as = As + cur * (BM * ASTR);
        const float* bs = Bs + cur * (16 * BSTR);

#pragma unroll
        for (int kk = 0; kk < 2; kk++) {
            unsigned af[MI][4], bf[4][2];
#pragma unroll
            for (int mi = 0; mi < MI; mi++) {
                int r = wm + mi * 16 + g;
                af[mi][0] = __float_as_uint(as[r * ASTR + kk * 8 + tig]);
                af[mi][1] = __float_as_uint(as[(r + 8) * ASTR + kk * 8 + tig]);
                af[mi][2] = __float_as_uint(as[r * ASTR + kk * 8 + tig + 4]);
                af[mi][3] = __float_as_uint(as[(r + 8) * ASTR + kk * 8 + tig + 4]);
            }
#pragma unroll
            for (int nj = 0; nj < 4; nj++) {
                int col = wn + nj * 8 + g;
                bf[nj][0] = __float_as_uint(bs[(kk * 8 + tig) * BSTR + col]);
                bf[nj][1] = __float_as_uint(bs[(kk * 8 + tig + 4) * BSTR + col]);
            }
#pragma unroll
            for (int mi = 0; mi < MI; mi++)
#pragma unroll
                for (int nj = 0; nj < 4; nj++)
                    asm volatile(
                        "mma.sync.aligned.m16n8k8.row.col.f32.tf32.tf32.f32 "
                        "{%0,%1,%2,%3},{%4,%5,%6,%7},{%8,%9},{%0,%1,%2,%3};\n"
                        : "+f"(acc[mi][nj][0]), "+f"(acc[mi][nj][1]),
                          "+f"(acc[mi][nj][2]), "+f"(acc[mi][nj][3])
                        : "r"(af[mi][0]), "r"(af[mi][1]), "r"(af[mi][2]), "r"(af[mi][3]),
                          "r"(bf[nj][0]), "r"(bf[nj][1]));
        }
    }

    // ---- epilogue ----
#pragma unroll
    for (int mi = 0; mi < MI; mi++) {
        int r0 = m0 + wm + mi * 16 + g;
#pragma unroll
        for (int nj = 0; nj < 4; nj++) {
            int col = n0 + wn + nj * 8 + 2 * tig;
#pragma unroll
            for (int half = 0; half < 2; half++) {
                int rr = r0 + half * 8;
#pragma unroll
                for (int jj = 0; jj < 2; jj++) {
                    int cc = col + jj;
                    if (cc < N) {
                        float v = acc[mi][nj][half * 2 + jj];
                        if (epi != 3) v += bias[cc];
                        if (epi == 1) v = tf32r(gelu_f(v));
                        long long o = (long long)rr * N + cc;
                        if (epi == 2) v += out[o];
                        out[o] = v;
                    }
                }
            }
        }
    }
}

// ---------------- tiled fp32 flash attention (tf32-rounded output) ----------------
__global__ void __launch_bounds__(256)
fattn_kernel(const float* __restrict__ qkv, float* __restrict__ out) {
    extern __shared__ float sm[];
    float (*sQt)[68] = (float(*)[68])(sm);
    float (*sKt)[68] = (float(*)[68])(sm + 64 * 68);
    float (*sV)[68]  = (float(*)[68])(sm + 2 * 64 * 68);
    float (*sP)[68]  = (float(*)[68])(sm + 3 * 64 * 68);

    int tid = threadIdx.x;
    int tx = tid & 15, ty = tid >> 4;
    int qt = (int)gridDim.x - 1 - (int)blockIdx.x;  // heavy tiles first
    int h = blockIdx.y, b = blockIdx.z;
    int q0 = qt * 64;

    {
        int r = tid >> 4;
        int c4 = (tid & 15) * 4;
#pragma unroll
        for (int rr = 0; rr < 64; rr += 16) {
            const float* qrow = qkv + (long long)(b * Tlen + q0 + r + rr) * C3 + h * HD;
            float4 v = *(const float4*)(qrow + c4);
            sQt[c4 + 0][r + rr] = v.x;
            sQt[c4 + 1][r + rr] = v.y;
            sQt[c4 + 2][r + rr] = v.z;
            sQt[c4 + 3][r + rr] = v.w;
        }
    }

    float O[4][4] = {};
    float m[4], l[4];
#pragma unroll
    for (int i = 0; i < 4; i++) { m[i] = -INFINITY; l[i] = 0.f; }

    const float scale = 0.125f;
    int ntiles = qt + 1;

    for (int kt = 0; kt < ntiles; kt++) {
        int kv0 = kt * 64;
        __syncthreads();
        {
            int r = tid >> 4;
            int c4 = (tid & 15) * 4;
#pragma unroll
            for (int rr0 = 0; rr0 < 64; rr0 += 16) {
                int rr = r + rr0;
                const float* krow = qkv + (long long)(b * Tlen + kv0 + rr) * C3 + C + h * HD;
                float4 kv4 = *(const float4*)(krow + c4);
                sKt[c4 + 0][rr] = kv4.x;
                sKt[c4 + 1][rr] = kv4.y;
                sKt[c4 + 2][rr] = kv4.z;
                sKt[c4 + 3][rr] = kv4.w;
                const float* vrow = qkv + (long long)(b * Tlen + kv0 + rr) * C3 + 2 * C + h * HD;
                *(float4*)&sV[rr][c4] = *(const float4*)(vrow + c4);
            }
        }
        __syncthreads();

        float s[4][4] = {};
#pragma unroll 16
        for (int kk = 0; kk < 64; kk++) {
            float4 a = *(const float4*)&sQt[kk][ty * 4];
            float4 bv = *(const float4*)&sKt[kk][tx * 4];
            s[0][0] += a.x * bv.x; s[0][1] += a.x * bv.y; s[0][2] += a.x * bv.z; s[0][3] += a.x * bv.w;
            s[1][0] += a.y * bv.x; s[1][1] += a.y * bv.y; s[1][2] += a.y * bv.z; s[1][3] += a.y * bv.w;
            s[2][0] += a.z * bv.x; s[2][1] += a.z * bv.y; s[2][2] += a.z * bv.z; s[2][3] += a.z * bv.w;
            s[3][0] += a.w * bv.x; s[3][1] += a.w * bv.y; s[3][2] += a.w * bv.z; s[3][3] += a.w * bv.w;
        }
#pragma unroll
        for (int i = 0; i < 4; i++)
#pragma unroll
            for (int j = 0; j < 4; j++) s[i][j] *= scale;

        if (kt == qt) {
#pragma unroll
            for (int i = 0; i < 4; i++) {
                int qg = q0 + ty * 4 + i;
#pragma unroll
                for (int j = 0; j < 4; j++)
                    if (kv0 + tx * 4 + j > qg) s[i][j] = -INFINITY;
            }
        }

#pragma unroll
        for (int i = 0; i < 4; i++) {
            float rm = fmaxf(fmaxf(s[i][0], s[i][1]), fmaxf(s[i][2], s[i][3]));
#pragma unroll
            for (int off = 1; off < 16; off <<= 1)
                rm = fmaxf(rm, __shfl_xor_sync(0xFFFFFFFFu, rm, off));
            float mn = fmaxf(m[i], rm);
            float cs = __expf(m[i] - mn);
            float p0 = __expf(s[i][0] - mn);
            float p1 = __expf(s[i][1] - mn);
            float p2 = __expf(s[i][2] - mn);
            float p3 = __expf(s[i][3] - mn);
            float rs = (p0 + p1) + (p2 + p3);
#pragma unroll
            for (int off = 1; off < 16; off <<= 1)
                rs += __shfl_xor_sync(0xFFFFFFFFu, rs, off);
            l[i] = l[i] * cs + rs;
            m[i] = mn;
            O[i][0] *= cs; O[i][1] *= cs; O[i][2] *= cs; O[i][3] *= cs;
            sP[ty * 4 + i][tx * 4 + 0] = p0;
            sP[ty * 4 + i][tx * 4 + 1] = p1;
            sP[ty * 4 + i][tx * 4 + 2] = p2;
            sP[ty * 4 + i][tx * 4 + 3] = p3;
        }
        __syncthreads();

#pragma unroll 8
        for (int kv = 0; kv < 64; kv++) {
            float4 v = *(const float4*)&sV[kv][tx * 4];
            float p0 = sP[ty * 4 + 0][kv];
            float p1 = sP[ty * 4 + 1][kv];
            float p2 = sP[ty * 4 + 2][kv];
            float p3 = sP[ty * 4 + 3][kv];
            O[0][0] += p0 * v.x; O[0][1] += p0 * v.y; O[0][2] += p0 * v.z; O[0][3] += p0 * v.w;
            O[1][0] += p1 * v.x; O[1][1] += p1 * v.y; O[1][2] += p1 * v.z; O[1][3] += p1 * v.w;
            O[2][0] += p2 * v.x; O[2][1] += p2 * v.y; O[2][2] += p2 * v.z; O[2][3] += p2 * v.w;
            O[3][0] += p3 * v.x; O[3][1] += p3 * v.y; O[3][2] += p3 * v.z; O[3][3] += p3 * v.w;
        }
    }

#pragma unroll
    for (int i = 0; i < 4; i++) {
        float inv = 1.f / l[i];
        float4 o4;
        o4.x = tf32r(O[i][0] * inv); o4.y = tf32r(O[i][1] * inv);
        o4.z = tf32r(O[i][2] * inv); o4.w = tf32r(O[i][3] * inv);
        float* o = out + (long long)(b * Tlen + q0 + ty * 4 + i) * C + h * HD + tx * 4;
        *(float4*)o = o4;
    }
}

// ---------------- driver ----------------
#define GEMM_SMEM(BM) (3 * ((BM) * ASTR + 16 * BSTR) * (int)sizeof(float))
#define ATTN_SMEM (4 * 64 * 68 * (int)sizeof(float))

extern "C" void kernel_launch(void* const* d_in, const int* in_sizes, int n_in,
                              void* d_out, int out_size) {
    const int*   idx      = (const int*)  d_in[0];
    const float* wte      = (const float*)d_in[1];
    const float* wpe      = (const float*)d_in[2];
    const float* ln1_w    = (const float*)d_in[3];
    const float* ln1_b    = (const float*)d_in[4];
    const float* attn_w   = (const float*)d_in[5];
    const float* attn_b   = (const float*)d_in[6];
    const float* proj_w   = (const float*)d_in[7];
    const float* proj_b   = (const float*)d_in[8];
    const float* ln2_w    = (const float*)d_in[9];
    const float* ln2_b    = (const float*)d_in[10];
    const float* fc_w     = (const float*)d_in[11];
    const float* fc_b     = (const float*)d_in[12];
    const float* fcproj_w = (const float*)d_in[13];
    const float* fcproj_b = (const float*)d_in[14];
    const float* lnf_w    = (const float*)d_in[15];
    const float* lnf_b    = (const float*)d_in[16];
    const float* lm_head  = (const float*)d_in[17];
    float* out = (float*)d_out;

    float *x, *ln, *qkv, *atty, *hbuf, *wpad, *wq, *wp, *wf, *wfp;
    cudaGetSymbolAddress((void**)&x,    g_x);
    cudaGetSymbolAddress((void**)&ln,   g_ln);
    cudaGetSymbolAddress((void**)&qkv,  g_qkv);
    cudaGetSymbolAddress((void**)&atty, g_atty);
    cudaGetSymbolAddress((void**)&hbuf, g_h);
    cudaGetSymbolAddress((void**)&wpad, g_wpad);
    cudaGetSymbolAddress((void**)&wq,   g_wqkv);
    cudaGetSymbolAddress((void**)&wp,   g_wproj);
    cudaGetSymbolAddress((void**)&wf,   g_wfc);
    cudaGetSymbolAddress((void**)&wfp,  g_wfp);

    cudaFuncSetAttribute(tgemm_kernel<128>,
                         cudaFuncAttributeMaxDynamicSharedMemorySize, GEMM_SMEM(128));
    cudaFuncSetAttribute(tgemm_kernel<64>,
                         cudaFuncAttributeMaxDynamicSharedMemorySize, GEMM_SMEM(64));
    cudaFuncSetAttribute(fattn_kernel,
                         cudaFuncAttributeMaxDynamicSharedMemorySize, ATTN_SMEM);

    // one-time per-launch weight rounding
    {
        long long n4;
        n4 = (long long)NL * C * C3 / 4;
        cvtw_kernel<<<(int)((n4 + 255) / 256), 256>>>(attn_w, wq, n4);
        n4 = (long long)NL * C * C / 4;
        cvtw_kernel<<<(int)((n4 + 255) / 256), 256>>>(proj_w, wp, n4);
        n4 = (long long)NL * C * C4 / 4;
        cvtw_kernel<<<(int)((n4 + 255) / 256), 256>>>(fc_w, wf, n4);
        n4 = (long long)NL * C4 * C / 4;
        cvtw_kernel<<<(int)((n4 + 255) / 256), 256>>>(fcproj_w, wfp, n4);
    }
    padw_kernel<<<dim3((VP + 255) / 256, C), 256>>>(lm_head, wpad);
    embed_kernel<<<BT, 256>>>(idx, wte, wpe, x);

    for (int l = 0; l < NL; l++) {
        ln_kernel<<<BT, 256>>>(x, ln1_w + l * C, ln1_b + l * C, ln);
        tgemm_kernel<128><<<dim3(C3 / 128, BT / 128), 256, GEMM_SMEM(128)>>>(
            ln, wq + (long long)l * C * C3, attn_b + l * C3, qkv, BT, C3, C, C3, 0);
        fattn_kernel<<<dim3(Tlen / 64, H, Bsz), 256, ATTN_SMEM>>>(qkv, atty);
        tgemm_kernel<64><<<dim3(C / 128, BT / 64), 256, GEMM_SMEM(64)>>>(
            atty, wp + (long long)l * C * C, proj_b + l * C, x, BT, C, C, C, 2);
        ln_kernel<<<BT, 256>>>(x, ln2_w + l * C, ln2_b + l * C, ln);
        tgemm_kernel<128><<<dim3(C4 / 128, BT / 128), 256, GEMM_SMEM(128)>>>(
            ln, wf + (long long)l * C * C4, fc_b + l * C4, hbuf, BT, C4, C, C4, 1);
        tgemm_kernel<64><<<dim3(C / 128, BT / 64), 256, GEMM_SMEM(64)>>>(
            hbuf, wfp + (long long)l * C4 * C, fcproj_b + l * C, x, BT, C, C4, C, 2);
    }

    ln_kernel<<<BT, 256>>>(x, lnf_w, lnf_b, ln);
    tgemm_kernel<128><<<dim3(VP / 128, BT / 128), 256, GEMM_SMEM(128)>>>(
        ln, wpad, (const float*)nullptr, out, BT, V, C, VP, 3);
}